// round 4
// baseline (speedup 1.0000x reference)
#include <cuda_runtime.h>
#include <math.h>
#include <float.h>

// Problem constants
#define BB   2
#define NNN  2048
#define DD   512
#define FFN  2048
#define KNN  16
#define MM   (BB*NNN)   // 4096 rows

// ---------------- scratch (device globals; no runtime allocation) ----------
__device__ float g_xn  [MM*DD];
__device__ float g_q   [MM*DD];
__device__ float g_k   [MM*DD];
__device__ float g_v   [MM*DD];
__device__ float g_attn[MM*DD];
__device__ float g_x1  [MM*DD];
__device__ float g_h   [MM*DD];
__device__ float g_mid [MM*FFN];
__device__ float g_S   [BB*NNN*NNN];   // pairwise inner products P P^T
__device__ float g_p2  [MM];
__device__ float g_sp  [MM];
__device__ int   g_idx [MM*KNN];

// ---------------- helpers --------------------------------------------------
__device__ __forceinline__ float warpReduceSum(float v) {
#pragma unroll
    for (int o = 16; o > 0; o >>= 1) v += __shfl_xor_sync(0xffffffffu, v, o);
    return v;
}

__device__ __forceinline__ float gelu_tanh(float x) {
    float x3 = x * x * x;
    return 0.5f * x * (1.f + tanhf(0.7978845608028654f * (x + 0.044715f * x3)));
}

// ---------------- LayerNorm (row = 512) ------------------------------------
__global__ void __launch_bounds__(256) ln_kernel(
    const float* __restrict__ X, const float* __restrict__ s,
    const float* __restrict__ bb, float* __restrict__ Y)
{
    int row = blockIdx.x, tid = threadIdx.x;
    const float* xr = X + (size_t)row * DD;
    float v0 = xr[tid], v1 = xr[tid + 256];
    float sm = v0 + v1, sq = v0 * v0 + v1 * v1;
    __shared__ float sh[16];
    int lane = tid & 31, w = tid >> 5;
    sm = warpReduceSum(sm); sq = warpReduceSum(sq);
    if (lane == 0) { sh[w] = sm; sh[8 + w] = sq; }
    __syncthreads();
    float tot = 0.f, tot2 = 0.f;
#pragma unroll
    for (int ww = 0; ww < 8; ww++) { tot += sh[ww]; tot2 += sh[8 + ww]; }
    float mean = tot * (1.f / DD);
    float var  = tot2 * (1.f / DD) - mean * mean;
    float rstd = rsqrtf(var + 1e-6f);
    float* yr = Y + (size_t)row * DD;
    yr[tid]       = s[tid]       * (v0 - mean) * rstd + bb[tid];
    yr[tid + 256] = s[tid + 256] * (v1 - mean) * rstd + bb[tid + 256];
}

// ---------------- position stats: p2 = sum p^2, sp = sum p ------------------
__global__ void __launch_bounds__(256) pos_stats_kernel(
    const float* __restrict__ P, float* __restrict__ p2, float* __restrict__ sp)
{
    int row = blockIdx.x, tid = threadIdx.x;
    const float* xr = P + (size_t)row * DD;
    float v0 = xr[tid], v1 = xr[tid + 256];
    float sm = v0 + v1, sq = v0 * v0 + v1 * v1;
    __shared__ float sh[16];
    int lane = tid & 31, w = tid >> 5;
    sm = warpReduceSum(sm); sq = warpReduceSum(sq);
    if (lane == 0) { sh[w] = sm; sh[8 + w] = sq; }
    __syncthreads();
    if (tid == 0) {
        float tot = 0.f, tot2 = 0.f;
#pragma unroll
        for (int ww = 0; ww < 8; ww++) { tot += sh[ww]; tot2 += sh[8 + ww]; }
        sp[row] = tot;
        p2[row] = tot2;
    }
}

// ---------------- generic SGEMM: C = A*W + bias (+res) (+gelu) --------------
// 128x128 block tile, BK=8, 256 threads, 8x8 per thread.
template<int DO_GELU, int HAS_RES>
__global__ void __launch_bounds__(256) gemm_kernel(
    const float* __restrict__ A, const float* __restrict__ W,
    const float* __restrict__ bias, const float* __restrict__ R,
    float* __restrict__ C, int M, int Nc, int Kc)
{
    __shared__ __align__(16) float As[8][128];
    __shared__ __align__(16) float Bs[8][128];
    const int tid = threadIdx.x;
    const int rowBase = blockIdx.y * 128, colBase = blockIdx.x * 128;
    const int tx = tid & 15, ty = tid >> 4;
    const int arow = tid >> 1, ak = (tid & 1) * 4;
    const int brow = tid >> 5, bcol = (tid & 31) * 4;
    const float* Ap = A + (size_t)(rowBase + arow) * Kc + ak;
    const float* Wp = W + (size_t)brow * Nc + colBase + bcol;
    float acc[8][8];
#pragma unroll
    for (int i = 0; i < 8; i++)
#pragma unroll
        for (int j = 0; j < 8; j++) acc[i][j] = 0.f;

    for (int k0 = 0; k0 < Kc; k0 += 8) {
        float4 av = *(const float4*)(Ap + k0);
        float4 bv = *(const float4*)(Wp + (size_t)k0 * Nc);
        As[ak + 0][arow] = av.x; As[ak + 1][arow] = av.y;
        As[ak + 2][arow] = av.z; As[ak + 3][arow] = av.w;
        *(float4*)(&Bs[brow][bcol]) = bv;
        __syncthreads();
#pragma unroll
        for (int kk = 0; kk < 8; kk++) {
            float4 a0 = *(const float4*)(&As[kk][ty * 8]);
            float4 a1 = *(const float4*)(&As[kk][ty * 8 + 4]);
            float4 b0 = *(const float4*)(&Bs[kk][tx * 8]);
            float4 b1 = *(const float4*)(&Bs[kk][tx * 8 + 4]);
            float ar[8] = {a0.x, a0.y, a0.z, a0.w, a1.x, a1.y, a1.z, a1.w};
            float br[8] = {b0.x, b0.y, b0.z, b0.w, b1.x, b1.y, b1.z, b1.w};
#pragma unroll
            for (int i = 0; i < 8; i++)
#pragma unroll
                for (int j = 0; j < 8; j++) acc[i][j] += ar[i] * br[j];
        }
        __syncthreads();
    }

#pragma unroll
    for (int i = 0; i < 8; i++) {
        int r = rowBase + ty * 8 + i;
        size_t rb = (size_t)r * Nc;
#pragma unroll
        for (int j = 0; j < 8; j += 4) {
            int cc = colBase + tx * 8 + j;
            float4 o;
            float v0 = acc[i][j + 0] + bias[cc + 0];
            float v1 = acc[i][j + 1] + bias[cc + 1];
            float v2 = acc[i][j + 2] + bias[cc + 2];
            float v3 = acc[i][j + 3] + bias[cc + 3];
            if (HAS_RES) {
                v0 += R[rb + cc + 0]; v1 += R[rb + cc + 1];
                v2 += R[rb + cc + 2]; v3 += R[rb + cc + 3];
            }
            if (DO_GELU) {
                v0 = gelu_tanh(v0); v1 = gelu_tanh(v1);
                v2 = gelu_tanh(v2); v3 = gelu_tanh(v3);
            }
            o.x = v0; o.y = v1; o.z = v2; o.w = v3;
            *(float4*)(&C[rb + cc]) = o;
        }
    }
}

// ---------------- NT GEMM for S = P P^T (symmetric: upper tiles + mirror) ---
__global__ void __launch_bounds__(256) gemm_nt_kernel(
    const float* __restrict__ P, float* __restrict__ S)
{
    if (blockIdx.y > blockIdx.x) return;   // compute tile (i<=j) only
    const float* Pb = P + (size_t)blockIdx.z * NNN * DD;
    float* Sb = S + (size_t)blockIdx.z * NNN * NNN;
    __shared__ __align__(16) float As[8][128];
    __shared__ __align__(16) float Bs[8][128];
    const int tid = threadIdx.x;
    const int rowBase = blockIdx.y * 128, colBase = blockIdx.x * 128;
    const int tx = tid & 15, ty = tid >> 4;
    const int arow = tid >> 1, ak = (tid & 1) * 4;
    const float* Ap = Pb + (size_t)(rowBase + arow) * DD + ak;
    const float* Bp = Pb + (size_t)(colBase + arow) * DD + ak;
    float acc[8][8];
#pragma unroll
    for (int i = 0; i < 8; i++)
#pragma unroll
        for (int j = 0; j < 8; j++) acc[i][j] = 0.f;

    for (int k0 = 0; k0 < DD; k0 += 8) {
        float4 av = *(const float4*)(Ap + k0);
        float4 bv = *(const float4*)(Bp + k0);
        As[ak + 0][arow] = av.x; As[ak + 1][arow] = av.y;
        As[ak + 2][arow] = av.z; As[ak + 3][arow] = av.w;
        Bs[ak + 0][arow] = bv.x; Bs[ak + 1][arow] = bv.y;
        Bs[ak + 2][arow] = bv.z; Bs[ak + 3][arow] = bv.w;
        __syncthreads();
#pragma unroll
        for (int kk = 0; kk < 8; kk++) {
            float4 a0 = *(const float4*)(&As[kk][ty * 8]);
            float4 a1 = *(const float4*)(&As[kk][ty * 8 + 4]);
            float4 b0 = *(const float4*)(&Bs[kk][tx * 8]);
            float4 b1 = *(const float4*)(&Bs[kk][tx * 8 + 4]);
            float ar[8] = {a0.x, a0.y, a0.z, a0.w, a1.x, a1.y, a1.z, a1.w};
            float br[8] = {b0.x, b0.y, b0.z, b0.w, b1.x, b1.y, b1.z, b1.w};
#pragma unroll
            for (int i = 0; i < 8; i++)
#pragma unroll
                for (int j = 0; j < 8; j++) acc[i][j] += ar[i] * br[j];
        }
        __syncthreads();
    }

#pragma unroll
    for (int i = 0; i < 8; i++) {
        int r = rowBase + ty * 8 + i;
        size_t rb = (size_t)r * NNN;
#pragma unroll
        for (int j = 0; j < 8; j += 4) {
            int cc = colBase + tx * 8 + j;
            float4 o;
            o.x = acc[i][j + 0]; o.y = acc[i][j + 1];
            o.z = acc[i][j + 2]; o.w = acc[i][j + 3];
            *(float4*)(&Sb[rb + cc]) = o;
        }
    }
    if (blockIdx.x != blockIdx.y) {   // mirror to lower triangle
#pragma unroll
        for (int i = 0; i < 8; i++) {
            int r = rowBase + ty * 8 + i;
#pragma unroll
            for (int j = 0; j < 8; j++) {
                int cc = colBase + tx * 8 + j;
                Sb[(size_t)cc * NNN + r] = acc[i][j];
            }
        }
    }
}

// ---------------- top-K=16 nearest (smallest diff_sq/den) -------------------
__global__ void __launch_bounds__(256) topk_kernel(
    const float* __restrict__ S, const float* __restrict__ p2,
    const float* __restrict__ cp, int* __restrict__ idx)
{
    __shared__ float rv[NNN];
    __shared__ float bmv[256];
    __shared__ int   bmi[256];
    int tid = threadIdx.x, row = blockIdx.x;
    int b = row >> 11, i = row & (NNN - 1);
    float c = *cp;
    float p2i = p2[row];
    float bi = 1.f - c * p2i;
    const float* Srow = S + ((size_t)b * NNN + i) * NNN;
    const float* p2b = p2 + b * NNN;
    for (int j = tid; j < NNN; j += 256) {
        float ip = Srow[j], p2j = p2b[j];
        float ds = fmaxf(p2i + p2j - 2.f * ip, 0.f);
        float den = fmaxf(bi * (1.f - c * p2j), 1e-8f);
        rv[j] = ds / den;
    }
    __syncthreads();
    for (int t = 0; t < KNN; t++) {
        float mv = FLT_MAX; int mi = 0x7fffffff;
        for (int j = tid; j < NNN; j += 256) {
            float v = rv[j];
            if (v < mv) { mv = v; mi = j; }
        }
        bmv[tid] = mv; bmi[tid] = mi;
        __syncthreads();
        for (int s = 128; s > 0; s >>= 1) {
            if (tid < s) {
                float v2 = bmv[tid + s]; int i2 = bmi[tid + s];
                if (v2 < bmv[tid] || (v2 == bmv[tid] && i2 < bmi[tid])) {
                    bmv[tid] = v2; bmi[tid] = i2;
                }
            }
            __syncthreads();
        }
        if (tid == 0) { idx[row * KNN + t] = bmi[0]; rv[bmi[0]] = FLT_MAX; }
        __syncthreads();
    }
}

// ---------------- fused geo-align + attention -------------------------------
// align computed analytically: m_d = (-a*qp_d + b*kp_d)/den is linear in the
// position rows, so all LN statistics of geo and the dot q.geo_ln reduce to
// scalars from p2, sp, ip and one per-neighbor dot (q*geo_s).pos_j.
__global__ void __launch_bounds__(256) attn_kernel(
    const float* __restrict__ q, const float* __restrict__ kmat,
    const float* __restrict__ vmat, const float* __restrict__ pos,
    const float* __restrict__ S, const float* __restrict__ p2,
    const float* __restrict__ sp, const int* __restrict__ idx,
    const float* __restrict__ geo_s, const float* __restrict__ geo_b,
    const float* __restrict__ cp, const float* __restrict__ as_p,
    const float* __restrict__ fs_p, float* __restrict__ attn)
{
    const int tid = threadIdx.x;
    const int row = blockIdx.x;
    const int b = row >> 11, i = row & (NNN - 1);
    __shared__ float qs[DD], us[DD];
    __shared__ int js[KNN];
    __shared__ float sh[24];
    __shared__ float shk[2][KNN][8];
    __shared__ float rowS[3];           // U, qb, uq
    __shared__ float sd[KNN], sf[KNN];
    __shared__ float ipk[KNN], p2k[KNN], spk[KNN];

    for (int d = tid; d < DD; d += 256) {
        float qv = q[(size_t)row * DD + d];
        qs[d] = qv; us[d] = qv * geo_s[d];
    }
    if (tid < KNN) js[tid] = idx[row * KNN + tid];
    __syncthreads();
    if (tid < KNN) {
        int j = js[tid];
        ipk[tid] = S[((size_t)b * NNN + i) * NNN + j];
        p2k[tid] = p2[b * NNN + j];
        spk[tid] = sp[b * NNN + j];
    }

    // row scalars: U = sum(q*geo_s), qb = q.geo_b, uq = (q*geo_s).pos_i
    const float* pi = pos + (size_t)row * DD;
    float pU = 0.f, pqb = 0.f, puq = 0.f;
    for (int d = tid; d < DD; d += 256) {
        float u = us[d];
        pU += u; pqb += qs[d] * geo_b[d]; puq += u * pi[d];
    }
    int lane = tid & 31, w = tid >> 5;
    pU = warpReduceSum(pU); pqb = warpReduceSum(pqb); puq = warpReduceSum(puq);
    if (lane == 0) { sh[w] = pU; sh[8 + w] = pqb; sh[16 + w] = puq; }
    __syncthreads();
    if (tid < 3) {
        float s = 0.f;
#pragma unroll
        for (int ww = 0; ww < 8; ww++) s += sh[tid * 8 + ww];
        rowS[tid] = s;
    }

    // per-neighbor dots: duk = (q*geo_s).pos_j, feat = q.k_j
    float pd[KNN], pf[KNN];
#pragma unroll
    for (int k = 0; k < KNN; k++) {
        int j = js[k];
        const float* pj = pos + ((size_t)b * NNN + j) * DD;
        const float* kj = kmat + ((size_t)b * NNN + j) * DD;
        float a = 0.f, f = 0.f;
        for (int d = tid; d < DD; d += 256) { a += us[d] * pj[d]; f += qs[d] * kj[d]; }
        pd[k] = a; pf[k] = f;
    }
#pragma unroll
    for (int k = 0; k < KNN; k++) { pd[k] = warpReduceSum(pd[k]); pf[k] = warpReduceSum(pf[k]); }
    if (lane == 0) {
#pragma unroll
        for (int k = 0; k < KNN; k++) { shk[0][k][w] = pd[k]; shk[1][k][w] = pf[k]; }
    }
    __syncthreads();
    if (tid < 32) {
        int which = tid >> 4, k = tid & 15;
        float s = 0.f;
#pragma unroll
        for (int ww = 0; ww < 8; ww++) s += shk[which][k][ww];
        if (which == 0) sd[k] = s; else sf[k] = s;
    }
    __syncthreads();

    // scalar math, redundantly in every thread (no more syncs needed)
    float c = *cp, sc = sqrtf(c);
    float alsc = *as_p, fesc = *fs_p;
    float p2i = p2[row], spi = sp[row];
    float U = rowS[0], qb = rowS[1], uq = rowS[2];
    float sco[KNN];
    float mx = -FLT_MAX;
#pragma unroll
    for (int k = 0; k < KNN; k++) {
        float ip = ipk[k], p2j = p2k[k], spj = spk[k];
        float alpha = 1.f - 2.f * c * ip + c * p2j;     // 1 + 2c<x,y> + c|y|^2, x=-qp
        float beta  = 1.f - c * p2i;                    // 1 - c|x|^2
        float den   = fmaxf(1.f - 2.f * c * ip + c * c * p2i * p2j, 1e-8f);
        float inv = 1.f / den;
        float Sm  = (beta * spj - alpha * spi) * inv;
        float Sm2 = fmaxf((alpha * alpha * p2i - 2.f * alpha * beta * ip
                           + beta * beta * p2j) * inv * inv, 0.f);
        float nrm = fmaxf(sqrtf(Sm2), 1e-8f);
        float arg = fminf(sc * nrm, 1.f - 1e-7f);
        float factor = atanhf(arg) / (sc * nrm);
        float Sg = factor * Sm, Sg2 = factor * factor * Sm2;
        float mean = Sg * (1.f / DD);
        float var = Sg2 * (1.f / DD) - mean * mean;
        float rstd = rsqrtf(var + 1e-6f);
        float Sug = factor * ((beta * sd[k] - alpha * uq) * inv);
        float align = rstd * (Sug - mean * U) + qb;
        float score = fesc * sf[k] + alsc * align;
        sco[k] = score;
        mx = fmaxf(mx, score);
    }
    float wgt[KNN];
    float sum = 0.f;
#pragma unroll
    for (int k = 0; k < KNN; k++) { wgt[k] = expf(sco[k] - mx); sum += wgt[k]; }
    float isum = 1.f / sum;

    for (int d = tid; d < DD; d += 256) {
        float acc = 0.f;
#pragma unroll
        for (int k = 0; k < KNN; k++)
            acc += wgt[k] * vmat[((size_t)b * NNN + js[k]) * DD + d];
        attn[(size_t)row * DD + d] = acc * isum;
    }
}

// ---------------- launch ----------------------------------------------------
extern "C" void kernel_launch(void* const* d_in, const int* in_sizes, int n_in,
                              void* d_out, int out_size)
{
    const float* x        = (const float*)d_in[0];
    const float* pos      = (const float*)d_in[1];
    const float* c        = (const float*)d_in[2];
    const float* Wq       = (const float*)d_in[3];
    const float* bq       = (const float*)d_in[4];
    const float* Wk       = (const float*)d_in[5];
    const float* bk       = (const float*)d_in[6];
    const float* Wv       = (const float*)d_in[7];
    const float* bv       = (const float*)d_in[8];
    const float* Wo       = (const float*)d_in[9];
    const float* bo       = (const float*)d_in[10];
    const float* W1       = (const float*)d_in[11];
    const float* b1       = (const float*)d_in[12];
    const float* W2       = (const float*)d_in[13];
    const float* b2       = (const float*)d_in[14];
    const float* ln1_s    = (const float*)d_in[15];
    const float* ln1_b    = (const float*)d_in[16];
    const float* ln2_s    = (const float*)d_in[17];
    const float* ln2_b    = (const float*)d_in[18];
    const float* geo_s    = (const float*)d_in[19];
    const float* geo_b    = (const float*)d_in[20];
    const float* al_sc    = (const float*)d_in[21];
    const float* fe_sc    = (const float*)d_in[22];
    float* out = (float*)d_out;

    float *xn, *q, *k, *v, *S, *p2, *sp, *attn, *x1, *h, *mid;
    int* idx;
    cudaGetSymbolAddress((void**)&xn,   g_xn);
    cudaGetSymbolAddress((void**)&q,    g_q);
    cudaGetSymbolAddress((void**)&k,    g_k);
    cudaGetSymbolAddress((void**)&v,    g_v);
    cudaGetSymbolAddress((void**)&S,    g_S);
    cudaGetSymbolAddress((void**)&p2,   g_p2);
    cudaGetSymbolAddress((void**)&sp,   g_sp);
    cudaGetSymbolAddress((void**)&attn, g_attn);
    cudaGetSymbolAddress((void**)&x1,   g_x1);
    cudaGetSymbolAddress((void**)&h,    g_h);
    cudaGetSymbolAddress((void**)&mid,  g_mid);
    cudaGetSymbolAddress((void**)&idx,  g_idx);

    // 1. LN1 and position stats
    ln_kernel<<<MM, 256>>>(x, ln1_s, ln1_b, xn);
    pos_stats_kernel<<<MM, 256>>>(pos, p2, sp);

    // 2. Q, K, V projections
    dim3 gqkv(DD / 128, MM / 128);
    gemm_kernel<0, 0><<<gqkv, 256>>>(xn, Wq, bq, nullptr, q, MM, DD, DD);
    gemm_kernel<0, 0><<<gqkv, 256>>>(xn, Wk, bk, nullptr, k, MM, DD, DD);
    gemm_kernel<0, 0><<<gqkv, 256>>>(xn, Wv, bv, nullptr, v, MM, DD, DD);

    // 3. S = P P^T (batched, symmetric)
    dim3 gnt(NNN / 128, NNN / 128, BB);
    gemm_nt_kernel<<<gnt, 256>>>(pos, S);

    // 4. top-16 neighbors
    topk_kernel<<<MM, 256>>>(S, p2, c, idx);

    // 5. fused geo-align + softmax + weighted sum
    attn_kernel<<<MM, 256>>>(q, k, v, pos, S, p2, sp, idx,
                             geo_s, geo_b, c, al_sc, fe_sc, attn);

    // 6. x1 = x + attn @ Wo + bo
    gemm_kernel<0, 1><<<gqkv, 256>>>(attn, Wo, bo, x, x1, MM, DD, DD);

    // 7. h = LN2(x1)
    ln_kernel<<<MM, 256>>>(x1, ln2_s, ln2_b, h);

    // 8. mid = gelu(h @ W1 + b1)
    dim3 gff1(FFN / 128, MM / 128);
    gemm_kernel<1, 0><<<gff1, 256>>>(h, W1, b1, nullptr, mid, MM, FFN, DD);

    // 9. out = x1 + mid @ W2 + b2
    dim3 gff2(DD / 128, MM / 128);
    gemm_kernel<0, 1><<<gff2, 256>>>(mid, W2, b2, x1, out, MM, DD, FFN);

    (void)in_sizes; (void)n_in; (void)out_size;
}

// round 5
// speedup vs baseline: 1.2453x; 1.2453x over previous
#include <cuda_runtime.h>
#include <math.h>
#include <float.h>

// Problem constants
#define BB   2
#define NNN  2048
#define DD   512
#define FFN  2048
#define KNN  16
#define MM   (BB*NNN)   // 4096 rows
#define QLD  1536       // packed QKV row stride

// ---------------- scratch (device globals; no runtime allocation) ----------
__device__ float g_xn  [MM*DD];
__device__ float g_qkv [MM*QLD];
__device__ float g_attn[MM*DD];
__device__ float g_x1  [MM*DD];
__device__ float g_h   [MM*DD];
__device__ float g_mid [MM*FFN];
__device__ float g_S   [BB*NNN*NNN];   // pairwise inner products P P^T
__device__ float g_p2  [MM];
__device__ float g_sp  [MM];
__device__ int   g_idx [MM*KNN];
__device__ float g_Wqkv[DD*QLD];
__device__ float g_bqkv[QLD];

// ---------------- helpers --------------------------------------------------
__device__ __forceinline__ float warpReduceSum(float v) {
#pragma unroll
    for (int o = 16; o > 0; o >>= 1) v += __shfl_xor_sync(0xffffffffu, v, o);
    return v;
}

__device__ __forceinline__ float gelu_tanh(float x) {
    float x3 = x * x * x;
    return 0.5f * x * (1.f + tanhf(0.7978845608028654f * (x + 0.044715f * x3)));
}

// ---------------- pack Wq|Wk|Wv into one [512,1536] matrix ------------------
__global__ void __launch_bounds__(256) pack_qkv_kernel(
    const float* __restrict__ Wq, const float* __restrict__ Wk,
    const float* __restrict__ Wv, const float* __restrict__ bq,
    const float* __restrict__ bk, const float* __restrict__ bv,
    float* __restrict__ Wp, float* __restrict__ bp)
{
    int i = blockIdx.x * 256 + threadIdx.x;
    if (i < DD * DD) {
        int k = i >> 9, n = i & 511;
        size_t o = (size_t)k * QLD + n;
        Wp[o]        = Wq[i];
        Wp[o + 512]  = Wk[i];
        Wp[o + 1024] = Wv[i];
    }
    if (i < DD) { bp[i] = bq[i]; bp[i + 512] = bk[i]; bp[i + 1024] = bv[i]; }
}

// ---------------- LayerNorm (row = 512) ------------------------------------
__global__ void __launch_bounds__(256) ln_kernel(
    const float* __restrict__ X, const float* __restrict__ s,
    const float* __restrict__ bb, float* __restrict__ Y)
{
    int row = blockIdx.x, tid = threadIdx.x;
    const float* xr = X + (size_t)row * DD;
    float v0 = xr[tid], v1 = xr[tid + 256];
    float sm = v0 + v1, sq = v0 * v0 + v1 * v1;
    __shared__ float sh[16];
    int lane = tid & 31, w = tid >> 5;
    sm = warpReduceSum(sm); sq = warpReduceSum(sq);
    if (lane == 0) { sh[w] = sm; sh[8 + w] = sq; }
    __syncthreads();
    float tot = 0.f, tot2 = 0.f;
#pragma unroll
    for (int ww = 0; ww < 8; ww++) { tot += sh[ww]; tot2 += sh[8 + ww]; }
    float mean = tot * (1.f / DD);
    float var  = tot2 * (1.f / DD) - mean * mean;
    float rstd = rsqrtf(var + 1e-6f);
    float* yr = Y + (size_t)row * DD;
    yr[tid]       = s[tid]       * (v0 - mean) * rstd + bb[tid];
    yr[tid + 256] = s[tid + 256] * (v1 - mean) * rstd + bb[tid + 256];
}

// ---------------- position stats: p2 = sum p^2, sp = sum p ------------------
__global__ void __launch_bounds__(256) pos_stats_kernel(
    const float* __restrict__ P, float* __restrict__ p2, float* __restrict__ sp)
{
    int row = blockIdx.x, tid = threadIdx.x;
    const float* xr = P + (size_t)row * DD;
    float v0 = xr[tid], v1 = xr[tid + 256];
    float sm = v0 + v1, sq = v0 * v0 + v1 * v1;
    __shared__ float sh[16];
    int lane = tid & 31, w = tid >> 5;
    sm = warpReduceSum(sm); sq = warpReduceSum(sq);
    if (lane == 0) { sh[w] = sm; sh[8 + w] = sq; }
    __syncthreads();
    if (tid == 0) {
        float tot = 0.f, tot2 = 0.f;
#pragma unroll
        for (int ww = 0; ww < 8; ww++) { tot += sh[ww]; tot2 += sh[8 + ww]; }
        sp[row] = tot;
        p2[row] = tot2;
    }
}

// ---------------- double-buffered SGEMM: C = A*W + bias (+res)(+gelu) -------
// 128x128 block tile, BK=8, 256 threads, 8x8 per thread, 2-stage smem.
template<int DO_GELU, int HAS_RES>
__global__ void __launch_bounds__(256) gemm_kernel(
    const float* __restrict__ A, const float* __restrict__ W,
    const float* __restrict__ bias, const float* __restrict__ R,
    float* __restrict__ C, int M, int Nc, int Kc)
{
    __shared__ __align__(16) float As[2][8][128];
    __shared__ __align__(16) float Bs[2][8][128];
    const int tid = threadIdx.x;
    const int rowBase = blockIdx.y * 128, colBase = blockIdx.x * 128;
    const int tx = tid & 15, ty = tid >> 4;
    const int arow = tid >> 1, ak = (tid & 1) * 4;
    const int brow = tid >> 5, bcol = (tid & 31) * 4;
    const float* Ap = A + (size_t)(rowBase + arow) * Kc + ak;
    const float* Wp = W + (size_t)brow * Nc + colBase + bcol;
    float acc[8][8];
#pragma unroll
    for (int i = 0; i < 8; i++)
#pragma unroll
        for (int j = 0; j < 8; j++) acc[i][j] = 0.f;

    float4 av = *(const float4*)(Ap);
    float4 bv = *(const float4*)(Wp);
    As[0][ak + 0][arow] = av.x; As[0][ak + 1][arow] = av.y;
    As[0][ak + 2][arow] = av.z; As[0][ak + 3][arow] = av.w;
    *(float4*)(&Bs[0][brow][bcol]) = bv;
    __syncthreads();

    int buf = 0;
    for (int k0 = 8; k0 < Kc; k0 += 8) {
        av = *(const float4*)(Ap + k0);
        bv = *(const float4*)(Wp + (size_t)k0 * Nc);
#pragma unroll
        for (int kk = 0; kk < 8; kk++) {
            float4 a0 = *(const float4*)(&As[buf][kk][ty * 8]);
            float4 a1 = *(const float4*)(&As[buf][kk][ty * 8 + 4]);
            float4 b0 = *(const float4*)(&Bs[buf][kk][tx * 8]);
            float4 b1 = *(const float4*)(&Bs[buf][kk][tx * 8 + 4]);
            float ar[8] = {a0.x, a0.y, a0.z, a0.w, a1.x, a1.y, a1.z, a1.w};
            float br[8] = {b0.x, b0.y, b0.z, b0.w, b1.x, b1.y, b1.z, b1.w};
#pragma unroll
            for (int i = 0; i < 8; i++)
#pragma unroll
                for (int j = 0; j < 8; j++) acc[i][j] += ar[i] * br[j];
        }
        int nb = buf ^ 1;
        As[nb][ak + 0][arow] = av.x; As[nb][ak + 1][arow] = av.y;
        As[nb][ak + 2][arow] = av.z; As[nb][ak + 3][arow] = av.w;
        *(float4*)(&Bs[nb][brow][bcol]) = bv;
        __syncthreads();
        buf = nb;
    }
#pragma unroll
    for (int kk = 0; kk < 8; kk++) {
        float4 a0 = *(const float4*)(&As[buf][kk][ty * 8]);
        float4 a1 = *(const float4*)(&As[buf][kk][ty * 8 + 4]);
        float4 b0 = *(const float4*)(&Bs[buf][kk][tx * 8]);
        float4 b1 = *(const float4*)(&Bs[buf][kk][tx * 8 + 4]);
        float ar[8] = {a0.x, a0.y, a0.z, a0.w, a1.x, a1.y, a1.z, a1.w};
        float br[8] = {b0.x, b0.y, b0.z, b0.w, b1.x, b1.y, b1.z, b1.w};
#pragma unroll
        for (int i = 0; i < 8; i++)
#pragma unroll
            for (int j = 0; j < 8; j++) acc[i][j] += ar[i] * br[j];
    }

#pragma unroll
    for (int i = 0; i < 8; i++) {
        int r = rowBase + ty * 8 + i;
        size_t rb = (size_t)r * Nc;
#pragma unroll
        for (int j = 0; j < 8; j += 4) {
            int cc = colBase + tx * 8 + j;
            float4 o;
            float v0 = acc[i][j + 0] + bias[cc + 0];
            float v1 = acc[i][j + 1] + bias[cc + 1];
            float v2 = acc[i][j + 2] + bias[cc + 2];
            float v3 = acc[i][j + 3] + bias[cc + 3];
            if (HAS_RES) {
                v0 += R[rb + cc + 0]; v1 += R[rb + cc + 1];
                v2 += R[rb + cc + 2]; v3 += R[rb + cc + 3];
            }
            if (DO_GELU) {
                v0 = gelu_tanh(v0); v1 = gelu_tanh(v1);
                v2 = gelu_tanh(v2); v3 = gelu_tanh(v3);
            }
            o.x = v0; o.y = v1; o.z = v2; o.w = v3;
            *(float4*)(&C[rb + cc]) = o;
        }
    }
}

// ---------------- NT GEMM for S = P P^T (symmetric, double-buffered) --------
__global__ void __launch_bounds__(256) gemm_nt_kernel(
    const float* __restrict__ P, float* __restrict__ S)
{
    if (blockIdx.y > blockIdx.x) return;   // compute tile (i<=j) only
    const float* Pb = P + (size_t)blockIdx.z * NNN * DD;
    float* Sb = S + (size_t)blockIdx.z * NNN * NNN;
    __shared__ __align__(16) float As[2][8][128];
    __shared__ __align__(16) float Bs[2][8][128];
    const int tid = threadIdx.x;
    const int rowBase = blockIdx.y * 128, colBase = blockIdx.x * 128;
    const int tx = tid & 15, ty = tid >> 4;
    const int arow = tid >> 1, ak = (tid & 1) * 4;
    const float* Ap = Pb + (size_t)(rowBase + arow) * DD + ak;
    const float* Bp = Pb + (size_t)(colBase + arow) * DD + ak;
    float acc[8][8];
#pragma unroll
    for (int i = 0; i < 8; i++)
#pragma unroll
        for (int j = 0; j < 8; j++) acc[i][j] = 0.f;

    float4 av = *(const float4*)(Ap);
    float4 bv = *(const float4*)(Bp);
    As[0][ak + 0][arow] = av.x; As[0][ak + 1][arow] = av.y;
    As[0][ak + 2][arow] = av.z; As[0][ak + 3][arow] = av.w;
    Bs[0][ak + 0][arow] = bv.x; Bs[0][ak + 1][arow] = bv.y;
    Bs[0][ak + 2][arow] = bv.z; Bs[0][ak + 3][arow] = bv.w;
    __syncthreads();

    int buf = 0;
    for (int k0 = 8; k0 < DD; k0 += 8) {
        av = *(const float4*)(Ap + k0);
        bv = *(const float4*)(Bp + k0);
#pragma unroll
        for (int kk = 0; kk < 8; kk++) {
            float4 a0 = *(const float4*)(&As[buf][kk][ty * 8]);
            float4 a1 = *(const float4*)(&As[buf][kk][ty * 8 + 4]);
            float4 b0 = *(const float4*)(&Bs[buf][kk][tx * 8]);
            float4 b1 = *(const float4*)(&Bs[buf][kk][tx * 8 + 4]);
            float ar[8] = {a0.x, a0.y, a0.z, a0.w, a1.x, a1.y, a1.z, a1.w};
            float br[8] = {b0.x, b0.y, b0.z, b0.w, b1.x, b1.y, b1.z, b1.w};
#pragma unroll
            for (int i = 0; i < 8; i++)
#pragma unroll
                for (int j = 0; j < 8; j++) acc[i][j] += ar[i] * br[j];
        }
        int nb = buf ^ 1;
        As[nb][ak + 0][arow] = av.x; As[nb][ak + 1][arow] = av.y;
        As[nb][ak + 2][arow] = av.z; As[nb][ak + 3][arow] = av.w;
        Bs[nb][ak + 0][arow] = bv.x; Bs[nb][ak + 1][arow] = bv.y;
        Bs[nb][ak + 2][arow] = bv.z; Bs[nb][ak + 3][arow] = bv.w;
        __syncthreads();
        buf = nb;
    }
#pragma unroll
    for (int kk = 0; kk < 8; kk++) {
        float4 a0 = *(const float4*)(&As[buf][kk][ty * 8]);
        float4 a1 = *(const float4*)(&As[buf][kk][ty * 8 + 4]);
        float4 b0 = *(const float4*)(&Bs[buf][kk][tx * 8]);
        float4 b1 = *(const float4*)(&Bs[buf][kk][tx * 8 + 4]);
        float ar[8] = {a0.x, a0.y, a0.z, a0.w, a1.x, a1.y, a1.z, a1.w};
        float br[8] = {b0.x, b0.y, b0.z, b0.w, b1.x, b1.y, b1.z, b1.w};
#pragma unroll
        for (int i = 0; i < 8; i++)
#pragma unroll
            for (int j = 0; j < 8; j++) acc[i][j] += ar[i] * br[j];
    }

#pragma unroll
    for (int i = 0; i < 8; i++) {
        int r = rowBase + ty * 8 + i;
        size_t rb = (size_t)r * NNN;
#pragma unroll
        for (int j = 0; j < 8; j += 4) {
            int cc = colBase + tx * 8 + j;
            float4 o;
            o.x = acc[i][j + 0]; o.y = acc[i][j + 1];
            o.z = acc[i][j + 2]; o.w = acc[i][j + 3];
            *(float4*)(&Sb[rb + cc]) = o;
        }
    }
    if (blockIdx.x != blockIdx.y) {   // mirror to lower triangle
#pragma unroll
        for (int i = 0; i < 8; i++) {
            int r = rowBase + ty * 8 + i;
#pragma unroll
            for (int j = 0; j < 8; j++) {
                int cc = colBase + tx * 8 + j;
                Sb[(size_t)cc * NNN + r] = acc[i][j];
            }
        }
    }
}

// ---------------- top-K=16 nearest: warp-local top-16 then merge ------------
__global__ void __launch_bounds__(256) topk_kernel(
    const float* __restrict__ S, const float* __restrict__ p2,
    const float* __restrict__ cp, int* __restrict__ idx)
{
    const int tid = threadIdx.x, row = blockIdx.x;
    const int b = row >> 11, i = row & (NNN - 1);
    const int lane = tid & 31, w = tid >> 5;
    const float c = *cp;
    const float p2i = p2[row];
    const float bi = 1.f - c * p2i;
    const float* Srow = S + ((size_t)b * NNN + i) * NNN;
    const float* p2b = p2 + b * NNN;

    // each warp owns 256 contiguous j's, kept in registers
    float vals[8]; int inds[8];
    const int base = w * 256;
#pragma unroll
    for (int u = 0; u < 8; u++) {
        int j = base + u * 32 + lane;
        float ip = Srow[j], p2j = p2b[j];
        float ds = fmaxf(p2i + p2j - 2.f * ip, 0.f);
        float den = fmaxf(bi * (1.f - c * p2j), 1e-8f);
        vals[u] = ds / den;
        inds[u] = j;
    }

    __shared__ float cval[128];
    __shared__ int   cidx[128];
#pragma unroll
    for (int t = 0; t < KNN; t++) {
        float mv = vals[0]; int mi = inds[0];
#pragma unroll
        for (int u = 1; u < 8; u++)
            if (vals[u] < mv || (vals[u] == mv && inds[u] < mi)) { mv = vals[u]; mi = inds[u]; }
#pragma unroll
        for (int o = 16; o > 0; o >>= 1) {
            float ov = __shfl_xor_sync(0xffffffffu, mv, o);
            int   oi = __shfl_xor_sync(0xffffffffu, mi, o);
            if (ov < mv || (ov == mv && oi < mi)) { mv = ov; mi = oi; }
        }
#pragma unroll
        for (int u = 0; u < 8; u++)
            if (inds[u] == mi) vals[u] = FLT_MAX;
        if (lane == 0) { cval[w * 16 + t] = mv; cidx[w * 16 + t] = mi; }
    }
    __syncthreads();

    if (w == 0) {
        float mvals[4]; int minds[4];
#pragma unroll
        for (int u = 0; u < 4; u++) { mvals[u] = cval[lane + u * 32]; minds[u] = cidx[lane + u * 32]; }
#pragma unroll
        for (int t = 0; t < KNN; t++) {
            float mv = mvals[0]; int mi = minds[0];
#pragma unroll
            for (int u = 1; u < 4; u++)
                if (mvals[u] < mv || (mvals[u] == mv && minds[u] < mi)) { mv = mvals[u]; mi = minds[u]; }
#pragma unroll
            for (int o = 16; o > 0; o >>= 1) {
                float ov = __shfl_xor_sync(0xffffffffu, mv, o);
                int   oi = __shfl_xor_sync(0xffffffffu, mi, o);
                if (ov < mv || (ov == mv && oi < mi)) { mv = ov; mi = oi; }
            }
#pragma unroll
            for (int u = 0; u < 4; u++)
                if (minds[u] == mi) mvals[u] = FLT_MAX;
            if (lane == 0) idx[row * KNN + t] = mi;
        }
    }
}

// ---------------- fused geo-align + attention -------------------------------
// align computed analytically: m_d = (-a*qp_d + b*kp_d)/den is linear in the
// position rows, so all LN statistics of geo and the dot q.geo_ln reduce to
// scalars from p2, sp, ip and one per-neighbor dot (q*geo_s).pos_j.
__global__ void __launch_bounds__(256) attn_kernel(
    const float* __restrict__ qkv, const float* __restrict__ pos,
    const float* __restrict__ S, const float* __restrict__ p2,
    const float* __restrict__ sp, const int* __restrict__ idx,
    const float* __restrict__ geo_s, const float* __restrict__ geo_b,
    const float* __restrict__ cp, const float* __restrict__ as_p,
    const float* __restrict__ fs_p, float* __restrict__ attn)
{
    const int tid = threadIdx.x;
    const int row = blockIdx.x;
    const int b = row >> 11, i = row & (NNN - 1);
    __shared__ float qs[DD], us[DD];
    __shared__ int js[KNN];
    __shared__ float sh[24];
    __shared__ float shk[2][KNN][8];
    __shared__ float rowS[3];           // U, qb, uq
    __shared__ float sd[KNN], sf[KNN];
    __shared__ float ipk[KNN], p2k[KNN], spk[KNN];

    for (int d = tid; d < DD; d += 256) {
        float qv = qkv[(size_t)row * QLD + d];
        qs[d] = qv; us[d] = qv * geo_s[d];
    }
    if (tid < KNN) js[tid] = idx[row * KNN + tid];
    __syncthreads();
    if (tid < KNN) {
        int j = js[tid];
        ipk[tid] = S[((size_t)b * NNN + i) * NNN + j];
        p2k[tid] = p2[b * NNN + j];
        spk[tid] = sp[b * NNN + j];
    }

    // row scalars: U = sum(q*geo_s), qb = q.geo_b, uq = (q*geo_s).pos_i
    const float* pi = pos + (size_t)row * DD;
    float pU = 0.f, pqb = 0.f, puq = 0.f;
    for (int d = tid; d < DD; d += 256) {
        float u = us[d];
        pU += u; pqb += qs[d] * geo_b[d]; puq += u * pi[d];
    }
    int lane = tid & 31, w = tid >> 5;
    pU = warpReduceSum(pU); pqb = warpReduceSum(pqb); puq = warpReduceSum(puq);
    if (lane == 0) { sh[w] = pU; sh[8 + w] = pqb; sh[16 + w] = puq; }
    __syncthreads();
    if (tid < 3) {
        float s = 0.f;
#pragma unroll
        for (int ww = 0; ww < 8; ww++) s += sh[tid * 8 + ww];
        rowS[tid] = s;
    }

    // per-neighbor dots: duk = (q*geo_s).pos_j, feat = q.k_j
    float pd[KNN], pf[KNN];
#pragma unroll
    for (int k = 0; k < KNN; k++) {
        int j = js[k];
        const float* pj = pos + ((size_t)b * NNN + j) * DD;
        const float* kj = qkv + ((size_t)(b * NNN + j)) * QLD + 512;
        float a = 0.f, f = 0.f;
        for (int d = tid; d < DD; d += 256) { a += us[d] * pj[d]; f += qs[d] * kj[d]; }
        pd[k] = a; pf[k] = f;
    }
#pragma unroll
    for (int k = 0; k < KNN; k++) { pd[k] = warpReduceSum(pd[k]); pf[k] = warpReduceSum(pf[k]); }
    if (lane == 0) {
#pragma unroll
        for (int k = 0; k < KNN; k++) { shk[0][k][w] = pd[k]; shk[1][k][w] = pf[k]; }
    }
    __syncthreads();
    if (tid < 32) {
        int which = tid >> 4, k = tid & 15;
        float s = 0.f;
#pragma unroll
        for (int ww = 0; ww < 8; ww++) s += shk[which][k][ww];
        if (which == 0) sd[k] = s; else sf[k] = s;
    }
    __syncthreads();

    // scalar math, redundantly in every thread (no more syncs needed)
    float c = *cp, sc = sqrtf(c);
    float alsc = *as_p, fesc = *fs_p;
    float p2i = p2[row], spi = sp[row];
    float U = rowS[0], qb = rowS[1], uq = rowS[2];
    float sco[KNN];
    float mx = -FLT_MAX;
#pragma unroll
    for (int k = 0; k < KNN; k++) {
        float ip = ipk[k], p2j = p2k[k], spj = spk[k];
        float alpha = 1.f - 2.f * c * ip + c * p2j;     // 1 + 2c<x,y> + c|y|^2, x=-qp
        float beta  = 1.f - c * p2i;                    // 1 - c|x|^2
        float den   = fmaxf(1.f - 2.f * c * ip + c * c * p2i * p2j, 1e-8f);
        float inv = 1.f / den;
        float Sm  = (beta * spj - alpha * spi) * inv;
        float Sm2 = fmaxf((alpha * alpha * p2i - 2.f * alpha * beta * ip
                           + beta * beta * p2j) * inv * inv, 0.f);
        float nrm = fmaxf(sqrtf(Sm2), 1e-8f);
        float arg = fminf(sc * nrm, 1.f - 1e-7f);
        float factor = atanhf(arg) / (sc * nrm);
        float Sg = factor * Sm, Sg2 = factor * factor * Sm2;
        float mean = Sg * (1.f / DD);
        float var = Sg2 * (1.f / DD) - mean * mean;
        float rstd = rsqrtf(var + 1e-6f);
        float Sug = factor * ((beta * sd[k] - alpha * uq) * inv);
        float align = rstd * (Sug - mean * U) + qb;
        float score = fesc * sf[k] + alsc * align;
        sco[k] = score;
        mx = fmaxf(mx, score);
    }
    float wgt[KNN];
    float sum = 0.f;
#pragma unroll
    for (int k = 0; k < KNN; k++) { wgt[k] = expf(sco[k] - mx); sum += wgt[k]; }
    float isum = 1.f / sum;

    for (int d = tid; d < DD; d += 256) {
        float acc = 0.f;
#pragma unroll
        for (int k = 0; k < KNN; k++)
            acc += wgt[k] * qkv[((size_t)(b * NNN + js[k])) * QLD + 1024 + d];
        attn[(size_t)row * DD + d] = acc * isum;
    }
}

// ---------------- launch ----------------------------------------------------
extern "C" void kernel_launch(void* const* d_in, const int* in_sizes, int n_in,
                              void* d_out, int out_size)
{
    const float* x        = (const float*)d_in[0];
    const float* pos      = (const float*)d_in[1];
    const float* c        = (const float*)d_in[2];
    const float* Wq       = (const float*)d_in[3];
    const float* bq       = (const float*)d_in[4];
    const float* Wk       = (const float*)d_in[5];
    const float* bk       = (const float*)d_in[6];
    const float* Wv       = (const float*)d_in[7];
    const float* bv       = (const float*)d_in[8];
    const float* Wo       = (const float*)d_in[9];
    const float* bo       = (const float*)d_in[10];
    const float* W1       = (const float*)d_in[11];
    const float* b1       = (const float*)d_in[12];
    const float* W2       = (const float*)d_in[13];
    const float* b2       = (const float*)d_in[14];
    const float* ln1_s    = (const float*)d_in[15];
    const float* ln1_b    = (const float*)d_in[16];
    const float* ln2_s    = (const float*)d_in[17];
    const float* ln2_b    = (const float*)d_in[18];
    const float* geo_s    = (const float*)d_in[19];
    const float* geo_b    = (const float*)d_in[20];
    const float* al_sc    = (const float*)d_in[21];
    const float* fe_sc    = (const float*)d_in[22];
    float* out = (float*)d_out;

    float *xn, *qkv, *S, *p2, *sp, *attn, *x1, *h, *mid, *Wp, *bp;
    int* idx;
    cudaGetSymbolAddress((void**)&xn,   g_xn);
    cudaGetSymbolAddress((void**)&qkv,  g_qkv);
    cudaGetSymbolAddress((void**)&S,    g_S);
    cudaGetSymbolAddress((void**)&p2,   g_p2);
    cudaGetSymbolAddress((void**)&sp,   g_sp);
    cudaGetSymbolAddress((void**)&attn, g_attn);
    cudaGetSymbolAddress((void**)&x1,   g_x1);
    cudaGetSymbolAddress((void**)&h,    g_h);
    cudaGetSymbolAddress((void**)&mid,  g_mid);
    cudaGetSymbolAddress((void**)&idx,  g_idx);
    cudaGetSymbolAddress((void**)&Wp,   g_Wqkv);
    cudaGetSymbolAddress((void**)&bp,   g_bqkv);

    // 0. pack QKV weights
    pack_qkv_kernel<<<(DD * DD + 255) / 256, 256>>>(Wq, Wk, Wv, bq, bk, bv, Wp, bp);

    // 1. LN1 and position stats
    ln_kernel<<<MM, 256>>>(x, ln1_s, ln1_b, xn);
    pos_stats_kernel<<<MM, 256>>>(pos, p2, sp);

    // 2. fused QKV projection: [4096,512] @ [512,1536]
    dim3 gqkv(QLD / 128, MM / 128);
    gemm_kernel<0, 0><<<gqkv, 256>>>(xn, Wp, bp, nullptr, qkv, MM, QLD, DD);

    // 3. S = P P^T (batched, symmetric)
    dim3 gnt(NNN / 128, NNN / 128, BB);
    gemm_nt_kernel<<<gnt, 256>>>(pos, S);

    // 4. top-16 neighbors
    topk_kernel<<<MM, 256>>>(S, p2, c, idx);

    // 5. fused geo-align + softmax + weighted sum
    attn_kernel<<<MM, 256>>>(qkv, pos, S, p2, sp, idx,
                             geo_s, geo_b, c, al_sc, fe_sc, attn);

    // 6. x1 = x + attn @ Wo + bo
    dim3 go(DD / 128, MM / 128);
    gemm_kernel<0, 1><<<go, 256>>>(attn, Wo, bo, x, x1, MM, DD, DD);

    // 7. h = LN2(x1)
    ln_kernel<<<MM, 256>>>(x1, ln2_s, ln2_b, h);

    // 8. mid = gelu(h @ W1 + b1)
    dim3 gff1(FFN / 128, MM / 128);
    gemm_kernel<1, 0><<<gff1, 256>>>(h, W1, b1, nullptr, mid, MM, FFN, DD);

    // 9. out = x1 + mid @ W2 + b2
    dim3 gff2(DD / 128, MM / 128);
    gemm_kernel<0, 1><<<gff2, 256>>>(mid, W2, b2, x1, out, MM, DD, FFN);

    (void)in_sizes; (void)n_in; (void)out_size;
}